// round 1
// baseline (speedup 1.0000x reference)
#include <cuda_runtime.h>

// Problem sizes (fixed by the dataset)
#define BB 16      // batch
#define TT 1024    // sequence
#define JJ 128     // input dim
#define HH 64      // hidden (complex) dim

// Scratch: Bx transposed to [b][h][t] so the scan reads contiguous rows.
__device__ float g_Bxt[BB * HH * TT];   // 4 MB static scratch (alloc-free rule)

// ---------------------------------------------------------------------------
// Packed f32x2 helpers (fma.rn.f32x2 doubles fp32 FMA throughput on sm_103a)
// ---------------------------------------------------------------------------
__device__ __forceinline__ unsigned long long pack2(float lo, float hi) {
    unsigned long long p;
    asm("mov.b64 %0, {%1, %2};" : "=l"(p) : "f"(lo), "f"(hi));
    return p;
}
__device__ __forceinline__ void fma2(unsigned long long& acc,
                                     unsigned long long a,
                                     unsigned long long b) {
    asm("fma.rn.f32x2 %0, %1, %2, %0;" : "+l"(acc) : "l"(a), "l"(b));
}
__device__ __forceinline__ void unpack2(unsigned long long p, float& lo, float& hi) {
    asm("mov.b64 {%0, %1}, %2;" : "=f"(lo), "=f"(hi) : "l"(p));
}

// ---------------------------------------------------------------------------
// Kernel 1: Bxt[b][h][t] = sum_j B[h][j] * x[b][t][j]
// Block tile: all 64 h x 64 t, 128 threads, thread tile 4h x 8t (f32x2-packed).
// j processed in two 64-wide chunks; smem transposed with pad-68 (conflict-free,
// 16B-aligned for LDS.128).
// ---------------------------------------------------------------------------
__global__ __launch_bounds__(128) void gemm_kernel(const float* __restrict__ x,
                                                   const float* __restrict__ Bm) {
    __shared__ float Bs[64 * 68];   // [j_local][h], pad 68
    __shared__ float xs[64 * 68];   // [j_local][t], pad 68

    const int tid = threadIdx.x;
    const int ht  = tid >> 3;     // 0..15 -> h group of 4
    const int tt  = tid & 7;      // 0..7  -> t group of 8
    const int t0  = blockIdx.x * 64;
    const int b   = blockIdx.y;

    unsigned long long acc[4][4];
#pragma unroll
    for (int a = 0; a < 4; ++a)
#pragma unroll
        for (int p = 0; p < 4; ++p) acc[a][p] = 0ull;

    const float4* x4 = reinterpret_cast<const float4*>(x);
    const float4* B4 = reinterpret_cast<const float4*>(Bm);

    for (int jc = 0; jc < 2; ++jc) {
        if (jc) __syncthreads();
        // Load B chunk: 64 h rows x 16 float4 (64 j values), transpose to Bs[j][h]
#pragma unroll
        for (int i = 0; i < 8; ++i) {
            int f  = tid + 128 * i;        // 0..1023
            int h  = f >> 4;
            int jq = f & 15;
            float4 v = B4[h * 32 + jc * 16 + jq];
            Bs[(4 * jq + 0) * 68 + h] = v.x;
            Bs[(4 * jq + 1) * 68 + h] = v.y;
            Bs[(4 * jq + 2) * 68 + h] = v.z;
            Bs[(4 * jq + 3) * 68 + h] = v.w;
        }
        // Load x chunk: 64 t rows x 16 float4, transpose to xs[j][t]
#pragma unroll
        for (int i = 0; i < 8; ++i) {
            int f  = tid + 128 * i;
            int t  = f >> 4;
            int jq = f & 15;
            float4 v = x4[(b * TT + t0 + t) * 32 + jc * 16 + jq];
            xs[(4 * jq + 0) * 68 + t] = v.x;
            xs[(4 * jq + 1) * 68 + t] = v.y;
            xs[(4 * jq + 2) * 68 + t] = v.z;
            xs[(4 * jq + 3) * 68 + t] = v.w;
        }
        __syncthreads();

#pragma unroll 8
        for (int jj = 0; jj < 64; ++jj) {
            float4 bq  = *reinterpret_cast<const float4*>(&Bs[jj * 68 + ht * 4]);
            float4 xq0 = *reinterpret_cast<const float4*>(&xs[jj * 68 + tt * 8]);
            float4 xq1 = *reinterpret_cast<const float4*>(&xs[jj * 68 + tt * 8 + 4]);
            unsigned long long xp[4];
            xp[0] = pack2(xq0.x, xq0.y);
            xp[1] = pack2(xq0.z, xq0.w);
            xp[2] = pack2(xq1.x, xq1.y);
            xp[3] = pack2(xq1.z, xq1.w);
            unsigned long long bd[4];
            bd[0] = pack2(bq.x, bq.x);
            bd[1] = pack2(bq.y, bq.y);
            bd[2] = pack2(bq.z, bq.z);
            bd[3] = pack2(bq.w, bq.w);
#pragma unroll
            for (int a = 0; a < 4; ++a)
#pragma unroll
                for (int p = 0; p < 4; ++p) fma2(acc[a][p], bd[a], xp[p]);
        }
    }

    // Epilogue: write Bxt[b][h][t0 + tt*8 .. +7], coalesced per h-row.
#pragma unroll
    for (int a = 0; a < 4; ++a) {
        int h = ht * 4 + a;
        float r[8];
#pragma unroll
        for (int p = 0; p < 4; ++p) unpack2(acc[a][p], r[2 * p], r[2 * p + 1]);
        float* dst = &g_Bxt[(b * HH + h) * TT + t0 + tt * 8];
        *reinterpret_cast<float4*>(dst)     = make_float4(r[0], r[1], r[2], r[3]);
        *reinterpret_cast<float4*>(dst + 4) = make_float4(r[4], r[5], r[6], r[7]);
    }
}

// ---------------------------------------------------------------------------
// Kernel 2: complex linear scan  y_t = lam*y_{t-1} + Bx_t,  y_{-1} = 1.
// Block handles (b, 8 consecutive h). 256 threads = 32 t-chunks x 8 h.
// Each thread scans a 32-step chunk locally; carries combined with a
// per-h warp Kogge-Stone scan (constant multiplier lam^32).
// Layout (tg outer, h inner) makes output stores sector-efficient.
// ---------------------------------------------------------------------------
__global__ __launch_bounds__(256) void scan_kernel(const float* __restrict__ nu,
                                                   const float* __restrict__ theta,
                                                   float* __restrict__ out) {
    __shared__ float svr[32 * 9];   // [tg][h_local], pad 9
    __shared__ float svi[32 * 9];

    const int tid = threadIdx.x;
    const int tg  = tid >> 3;          // 0..31  t-chunk
    const int hl  = tid & 7;           // 0..7   h within group
    const int b   = blockIdx.y;
    const int hb  = blockIdx.x * 8;
    const int h   = hb + hl;

    // lam for this thread's h
    const float mag = expf(-expf(nu[h]));
    const float lr  = mag * cosf(theta[h]);
    const float li  = mag * sinf(theta[h]);

    // Load this thread's 32 inputs (contiguous, float4)
    float u[32];
    const float4* src = reinterpret_cast<const float4*>(&g_Bxt[(b * HH + h) * TT + tg * 32]);
#pragma unroll
    for (int q = 0; q < 8; ++q) {
        float4 v = src[q];
        u[4 * q + 0] = v.x; u[4 * q + 1] = v.y;
        u[4 * q + 2] = v.z; u[4 * q + 3] = v.w;
    }

    // Phase A: local scan with zero initial state -> chunk value V
    float yr = 0.f, yi = 0.f;
#pragma unroll
    for (int k = 0; k < 32; ++k) {
        float nyr = fmaf(lr, yr, fmaf(-li, yi, u[k]));
        float nyi = fmaf(lr, yi, li * yr);
        yr = nyr; yi = nyi;
    }
    svr[tg * 9 + hl] = yr;
    svi[tg * 9 + hl] = yi;
    __syncthreads();

    // Phase B: warp w scans the 32 chunk carries of h = hb + w.
    const int lane = tid & 31;
    const int wid  = tid >> 5;          // 0..7, exactly 8 warps
    const int h2   = hb + wid;
    const float mag2 = expf(-expf(nu[h2]));
    float ar = mag2 * cosf(theta[h2]);
    float ai = mag2 * sinf(theta[h2]);

    // lam^32 via 5 squarings
    float pr = ar, pi = ai;
#pragma unroll
    for (int s = 0; s < 5; ++s) {
        float nr = pr * pr - pi * pi;
        float ni = 2.f * pr * pi;
        pr = nr; pi = ni;
    }
    // P[d] = (lam^32)^(2^d)
    float Pr[5], Pi[5];
    Pr[0] = pr; Pi[0] = pi;
#pragma unroll
    for (int d = 1; d < 5; ++d) {
        Pr[d] = Pr[d - 1] * Pr[d - 1] - Pi[d - 1] * Pi[d - 1];
        Pi[d] = 2.f * Pr[d - 1] * Pi[d - 1];
    }

    float Vr = svr[lane * 9 + wid];
    float Vi = svi[lane * 9 + wid];
    // Kogge-Stone inclusive scan: V_i <- V_i + P^(2^d) * V_{i-2^d}
#pragma unroll
    for (int d = 0; d < 5; ++d) {
        int sh = 1 << d;
        float orr = __shfl_up_sync(0xffffffffu, Vr, sh);
        float oii = __shfl_up_sync(0xffffffffu, Vi, sh);
        if (lane >= sh) {
            float nVr = Vr + (Pr[d] * orr - Pi[d] * oii);
            float nVi = Vi + (Pr[d] * oii + Pi[d] * orr);
            Vr = nVr; Vi = nVi;
        }
    }
    // Exclusive
    float Wr = __shfl_up_sync(0xffffffffu, Vr, 1);
    float Wi = __shfl_up_sync(0xffffffffu, Vi, 1);
    if (lane == 0) { Wr = 0.f; Wi = 0.f; }
    // Incoming state S = (lam^32)^lane * y_{-1}(=1) + W
    float qr = 1.f, qi = 0.f;
#pragma unroll
    for (int d = 0; d < 5; ++d) {
        if ((lane >> d) & 1) {
            float nr = qr * Pr[d] - qi * Pi[d];
            float ni = qr * Pi[d] + qi * Pr[d];
            qr = nr; qi = ni;
        }
    }
    // Each warp owns one smem column -> no cross-warp race
    svr[lane * 9 + wid] = qr + Wr;
    svi[lane * 9 + wid] = qi + Wi;
    __syncthreads();

    // Phase C: re-run chunk with true incoming state; coalesced stores.
    yr = svr[tg * 9 + hl];
    yi = svi[tg * 9 + hl];
    float* op = out + (b * TT + tg * 32) * (2 * HH) + h;
#pragma unroll
    for (int k = 0; k < 32; ++k) {
        float nyr = fmaf(lr, yr, fmaf(-li, yi, u[k]));
        float nyi = fmaf(lr, yi, li * yr);
        yr = nyr; yi = nyi;
        op[k * 128]      = yr;   // real part at [b,t,h]
        op[k * 128 + 64] = yi;   // imag part at [b,t,H+h]
    }
}

// ---------------------------------------------------------------------------
extern "C" void kernel_launch(void* const* d_in, const int* in_sizes, int n_in,
                              void* d_out, int out_size) {
    const float* x     = (const float*)d_in[0];   // [16,1024,128]
    const float* Bm    = (const float*)d_in[1];   // [64,128]
    const float* nu    = (const float*)d_in[2];   // [64]
    const float* theta = (const float*)d_in[3];   // [64]
    float* out = (float*)d_out;                   // [16,1024,128]

    gemm_kernel<<<dim3(16, 16), 128>>>(x, Bm);
    scan_kernel<<<dim3(8, 16), 256>>>(nu, theta, out);
}

// round 2
// speedup vs baseline: 1.0865x; 1.0865x over previous
#include <cuda_runtime.h>

#define BB 16      // batch
#define TT 1024    // sequence
#define JJ 128     // input dim
#define HH 64      // hidden (complex) dim

// Scratch: Bx transposed to [b][h][t] so the scan reads contiguous rows.
__device__ float g_Bxt[BB * HH * TT];   // 4 MB static scratch

// ---------------------------------------------------------------------------
// f32x2 packed FMA (register-pair operands, no packing movs when operands
// come straight out of LDS.128 as ulonglong2 halves).
// ---------------------------------------------------------------------------
__device__ __forceinline__ void fma2(unsigned long long& acc,
                                     unsigned long long a,
                                     unsigned long long b) {
    asm("fma.rn.f32x2 %0, %1, %2, %0;" : "+l"(acc) : "l"(a), "l"(b));
}
__device__ __forceinline__ void unpack2(unsigned long long p, float& lo, float& hi) {
    asm("mov.b64 {%0, %1}, %2;" : "=f"(lo), "=f"(hi) : "l"(p));
}

// ---------------------------------------------------------------------------
// Kernel 1: Bxt[b][h][t] = sum_j B[h][j] * x[b][t][j]
// 128 blocks (1/SM), 128 threads, block tile 128t x 64h, thread tile 8t x 8h.
// K in 4 chunks of 32. Inner loop: 6 LDS.128 + 32 FFMA2, zero movs:
//   - x staged [j][t] (stride 132): LDS.128 -> 4 f32x2 pairs across t
//   - B staged duplicated [j][(h,h)] (group skew 20, stride 164):
//     LDS.128 -> dup pairs (b,b), broadcast across warp (2 distinct addrs)
// ---------------------------------------------------------------------------
#define XST 132
#define BST 164

__global__ __launch_bounds__(128) void gemm_kernel(const float* __restrict__ x,
                                                   const float* __restrict__ Bm) {
    __shared__ __align__(16) float xs[32 * XST];    // 16.5 KB
    __shared__ __align__(16) float bsd[32 * BST];   // 20.5 KB

    const int tid = threadIdx.x;
    const int tx  = tid & 15;     // t-group: 8 t each
    const int ty  = tid >> 4;     // h-group: 8 h each (0..7)
    const int b   = blockIdx.x >> 3;
    const int t0  = (blockIdx.x & 7) * 128;

    unsigned long long acc[8][4];
#pragma unroll
    for (int a = 0; a < 8; ++a)
#pragma unroll
        for (int p = 0; p < 4; ++p) acc[a][p] = 0ull;

    const float4* x4 = reinterpret_cast<const float4*>(x);
    const float4* B4 = reinterpret_cast<const float4*>(Bm);

    for (int jc = 0; jc < 4; ++jc) {
        if (jc) __syncthreads();
        // Stage x chunk: 128 t x 32 j -> xs[jl][t]
#pragma unroll
        for (int i = 0; i < 8; ++i) {
            int f  = tid + 128 * i;
            int t  = f >> 3;
            int jq = f & 7;
            float4 v = x4[(b * TT + t0 + t) * 32 + jc * 8 + jq];
            int base = (4 * jq) * XST + t;
            xs[base]           = v.x;
            xs[base + XST]     = v.y;
            xs[base + 2 * XST] = v.z;
            xs[base + 3 * XST] = v.w;
        }
        // Stage B chunk duplicated: 64 h x 32 j -> bsd[jl][grp*20 + pos*2 {dup}]
#pragma unroll
        for (int i = 0; i < 4; ++i) {
            int f  = tid + 128 * i;
            int h  = f >> 3;
            int jq = f & 7;
            float4 v  = B4[h * 32 + jc * 8 + jq];
            int   go  = (h >> 3) * 20 + (h & 7) * 2;
            int   rb  = (4 * jq) * BST + go;
            *reinterpret_cast<float2*>(&bsd[rb])           = make_float2(v.x, v.x);
            *reinterpret_cast<float2*>(&bsd[rb + BST])     = make_float2(v.y, v.y);
            *reinterpret_cast<float2*>(&bsd[rb + 2 * BST]) = make_float2(v.z, v.z);
            *reinterpret_cast<float2*>(&bsd[rb + 3 * BST]) = make_float2(v.w, v.w);
        }
        __syncthreads();

#pragma unroll 8
        for (int jj = 0; jj < 32; ++jj) {
            const ulonglong2* xr =
                reinterpret_cast<const ulonglong2*>(&xs[jj * XST + tx * 8]);
            ulonglong2 xa = xr[0];   // pairs (t0,t1),(t2,t3)
            ulonglong2 xb = xr[1];   // pairs (t4,t5),(t6,t7)
            const ulonglong2* br =
                reinterpret_cast<const ulonglong2*>(&bsd[jj * BST + ty * 20]);
            ulonglong2 b01 = br[0];  // dup (h0,h0),(h1,h1)
            ulonglong2 b23 = br[1];  // dup (h2,h2),(h3,h3)
            const ulonglong2* br2 =
                reinterpret_cast<const ulonglong2*>(&bsd[jj * BST + ty * 20 + 8]);
            ulonglong2 b45 = br2[0];
            ulonglong2 b67 = br2[1];

            unsigned long long xp[4] = {xa.x, xa.y, xb.x, xb.y};
            unsigned long long bd[8] = {b01.x, b01.y, b23.x, b23.y,
                                        b45.x, b45.y, b67.x, b67.y};
#pragma unroll
            for (int a = 0; a < 8; ++a)
#pragma unroll
                for (int p = 0; p < 4; ++p) fma2(acc[a][p], bd[a], xp[p]);
        }
    }

    // Epilogue: per h-row, 8 consecutive t -> 2 float4 stores (coalesced).
#pragma unroll
    for (int a = 0; a < 8; ++a) {
        float r[8];
#pragma unroll
        for (int p = 0; p < 4; ++p) unpack2(acc[a][p], r[2 * p], r[2 * p + 1]);
        float* dst = &g_Bxt[(b * HH + ty * 8 + a) * TT + t0 + tx * 8];
        *reinterpret_cast<float4*>(dst)     = make_float4(r[0], r[1], r[2], r[3]);
        *reinterpret_cast<float4*>(dst + 4) = make_float4(r[4], r[5], r[6], r[7]);
    }
}

// ---------------------------------------------------------------------------
// Kernel 2: complex linear scan  y_t = lam*y_{t-1} + Bx_t,  y_{-1} = 1.
// Block = (b, 8 h), 512 threads = 64 t-chunks x 8 h, chunk = 16 steps.
// Carry combine: 64 chunks/h split across 2 warps (low/high 32) with a
// smem bridge; per-warp Kogge-Stone with constant multiplier P = lam^16.
// ---------------------------------------------------------------------------
__global__ __launch_bounds__(512) void scan_kernel(const float* __restrict__ nu,
                                                   const float* __restrict__ theta,
                                                   float* __restrict__ out) {
    __shared__ float svr[64 * 9];
    __shared__ float svi[64 * 9];
    __shared__ float sbr[8], sbi[8];

    const int tid = threadIdx.x;
    const int tg  = tid >> 3;          // 0..63  t-chunk
    const int hl  = tid & 7;           // 0..7
    const int b   = blockIdx.y;
    const int hb  = blockIdx.x * 8;
    const int h   = hb + hl;

    const float mag = expf(-expf(nu[h]));
    const float lr  = mag * cosf(theta[h]);
    const float li  = mag * sinf(theta[h]);

    // Load 16 inputs (4 x LDG.128)
    float u[16];
    const float4* src =
        reinterpret_cast<const float4*>(&g_Bxt[(b * HH + h) * TT + tg * 16]);
#pragma unroll
    for (int q = 0; q < 4; ++q) {
        float4 v = src[q];
        u[4 * q + 0] = v.x; u[4 * q + 1] = v.y;
        u[4 * q + 2] = v.z; u[4 * q + 3] = v.w;
    }

    // Phase A: local scan from zero -> chunk value V
    float yr = 0.f, yi = 0.f;
#pragma unroll
    for (int k = 0; k < 16; ++k) {
        float nyr = fmaf(lr, yr, fmaf(-li, yi, u[k]));
        float nyi = fmaf(lr, yi, li * yr);
        yr = nyr; yi = nyi;
    }
    svr[tg * 9 + hl] = yr;
    svi[tg * 9 + hl] = yi;
    __syncthreads();

    // Phase B: warp (hw, half) scans chunks half*32 + lane of h = hb+hw.
    const int lane = tid & 31;
    const int wid  = tid >> 5;          // 0..15
    const int hw   = wid & 7;
    const int half = wid >> 3;
    const int c    = half * 32 + lane;

    const int   h2   = hb + hw;
    const float mag2 = expf(-expf(nu[h2]));
    float ar = mag2 * cosf(theta[h2]);
    float ai = mag2 * sinf(theta[h2]);

    // P = lam^16 via 4 squarings
    float pr = ar, pi = ai;
#pragma unroll
    for (int s = 0; s < 4; ++s) {
        float nr = pr * pr - pi * pi;
        float ni = 2.f * pr * pi;
        pr = nr; pi = ni;
    }
    float Pr[5], Pi[5];
    Pr[0] = pr; Pi[0] = pi;
#pragma unroll
    for (int d = 1; d < 5; ++d) {
        Pr[d] = Pr[d - 1] * Pr[d - 1] - Pi[d - 1] * Pi[d - 1];
        Pi[d] = 2.f * Pr[d - 1] * Pi[d - 1];
    }
    const float P32r = Pr[4] * Pr[4] - Pi[4] * Pi[4];
    const float P32i = 2.f * Pr[4] * Pi[4];

    float Vr = svr[c * 9 + hw];
    float Vi = svi[c * 9 + hw];
    // Kogge-Stone inclusive scan: V_i <- V_i + P^(2^d) * V_{i-2^d}
#pragma unroll
    for (int d = 0; d < 5; ++d) {
        int sh = 1 << d;
        float orr = __shfl_up_sync(0xffffffffu, Vr, sh);
        float oii = __shfl_up_sync(0xffffffffu, Vi, sh);
        if (lane >= sh) {
            float nVr = Vr + (Pr[d] * orr - Pi[d] * oii);
            float nVi = Vi + (Pr[d] * oii + Pi[d] * orr);
            Vr = nVr; Vi = nVi;
        }
    }
    // Bridge: inclusive total of low half -> high half's base
    if (half == 0 && lane == 31) { sbr[hw] = Vr; sbi[hw] = Vi; }
    __syncthreads();

    float Br_ = 1.f, Bi_ = 0.f;           // Base = E_{-1} = 1 for low half
    if (half) {                            // Base = E_31 = P^32 + Vtilde_31
        Br_ = P32r + sbr[hw];
        Bi_ = P32i + sbi[hw];
    }
    // Exclusive local prefix
    float Wr = __shfl_up_sync(0xffffffffu, Vr, 1);
    float Wi = __shfl_up_sync(0xffffffffu, Vi, 1);
    if (lane == 0) { Wr = 0.f; Wi = 0.f; }
    // P^lane
    float qr = 1.f, qi = 0.f;
#pragma unroll
    for (int d = 0; d < 5; ++d) {
        if ((lane >> d) & 1) {
            float nr = qr * Pr[d] - qi * Pi[d];
            float ni = qr * Pi[d] + qi * Pr[d];
            qr = nr; qi = ni;
        }
    }
    // Incoming state for chunk c: S = W + P^lane * Base
    svr[c * 9 + hw] = Wr + (qr * Br_ - qi * Bi_);
    svi[c * 9 + hw] = Wi + (qr * Bi_ + qi * Br_);
    __syncthreads();

    // Phase C: re-run chunk with true incoming state; stores (32B h-sectors).
    yr = svr[tg * 9 + hl];
    yi = svi[tg * 9 + hl];
    float* op = out + (b * TT + tg * 16) * (2 * HH) + h;
#pragma unroll
    for (int k = 0; k < 16; ++k) {
        float nyr = fmaf(lr, yr, fmaf(-li, yi, u[k]));
        float nyi = fmaf(lr, yi, li * yr);
        yr = nyr; yi = nyi;
        op[k * 128]      = yr;   // real at [b,t,h]
        op[k * 128 + 64] = yi;   // imag at [b,t,H+h]
    }
}

// ---------------------------------------------------------------------------
extern "C" void kernel_launch(void* const* d_in, const int* in_sizes, int n_in,
                              void* d_out, int out_size) {
    const float* x     = (const float*)d_in[0];   // [16,1024,128]
    const float* Bm    = (const float*)d_in[1];   // [64,128]
    const float* nu    = (const float*)d_in[2];   // [64]
    const float* theta = (const float*)d_in[3];   // [64]
    float* out = (float*)d_out;                   // [16,1024,128]

    gemm_kernel<<<128, 128>>>(x, Bm);
    scan_kernel<<<dim3(8, 16), 512>>>(nu, theta, out);
}